// round 2
// baseline (speedup 1.0000x reference)
#include <cuda_runtime.h>
#include <cstdint>

// DepthDCOp: out[n,c,h,w] = sum_{kh,kw} x_pad[n,c,h+kh-1,w+kw-1] * ker[n,0,kh*3+kw,h,w]
// Shapes fixed by setup_inputs(): N=8, C=256, H=64, W=64, K=3, dilation=1.

#define N_ 8
#define C_ 256
#define H_ 64
#define W_ 64
#define HW_ (H_ * W_)

__global__ __launch_bounds__(256, 8)
void ddf_kernel(const float* __restrict__ x,
                const float* __restrict__ ker,
                float* __restrict__ out)
{
    // gridDim.x = N*H (one (n,h) per block.x), gridDim.y = C/16 (16 channels per block)
    const int nh = blockIdx.x;
    const int n  = nh / H_;
    const int h  = nh % H_;
    const int tx = threadIdx.x;          // 0..15 -> w quad (w0 = 4*tx)
    const int ty = threadIdx.y;          // 0..15 -> channel within group
    const int tid = ty * 16 + tx;

    // Stage the 9 per-pixel kernel rows for this (n,h): 9*64 floats = 2.25 KB.
    // Shared by all 16 channels in the block (kernel is broadcast over C).
    __shared__ float sk[9][W_];
    {
        // 576 floats = 144 float4 loads; threads 0..143 each grab one.
        const float4* kp = reinterpret_cast<const float4*>(
            ker + (size_t)n * 9 * HW_ + (size_t)h * W_);
        if (tid < 144) {
            const int t = tid >> 4;          // tap 0..8
            const int q = tid & 15;          // quad within row
            reinterpret_cast<float4*>(&sk[t][0])[q] = kp[(size_t)t * (HW_ / 4) + q];
        }
    }
    __syncthreads();

    const int c  = (blockIdx.y << 4) + ty;
    const int w0 = tx << 2;

    const float* xb = x + (((size_t)n * C_ + c) * H_ + h) * W_;

    // Load 3 input rows, 6 elements each (w0-1 .. w0+4): float4 body + 2 halo scalars.
    float xr[3][6];
    #pragma unroll
    for (int r = 0; r < 3; r++) {
        const int hh = h + r - 1;
        const bool rowok = (hh >= 0) & (hh < H_);
        const float* xp = xb + (r - 1) * W_;
        if (rowok) {
            const float4 body = *reinterpret_cast<const float4*>(xp + w0);
            xr[r][1] = body.x; xr[r][2] = body.y; xr[r][3] = body.z; xr[r][4] = body.w;
            xr[r][0] = (w0 > 0)      ? xp[w0 - 1] : 0.0f;
            xr[r][5] = (w0 + 4 < W_) ? xp[w0 + 4] : 0.0f;
        } else {
            #pragma unroll
            for (int j = 0; j < 6; j++) xr[r][j] = 0.0f;
        }
    }

    float acc0 = 0.f, acc1 = 0.f, acc2 = 0.f, acc3 = 0.f;
    #pragma unroll
    for (int kh = 0; kh < 3; kh++) {
        #pragma unroll
        for (int kw = 0; kw < 3; kw++) {
            const int t = kh * 3 + kw;
            acc0 = fmaf(sk[t][w0 + 0], xr[kh][0 + kw], acc0);
            acc1 = fmaf(sk[t][w0 + 1], xr[kh][1 + kw], acc1);
            acc2 = fmaf(sk[t][w0 + 2], xr[kh][2 + kw], acc2);
            acc3 = fmaf(sk[t][w0 + 3], xr[kh][3 + kw], acc3);
        }
    }

    float4 o; o.x = acc0; o.y = acc1; o.z = acc2; o.w = acc3;
    *reinterpret_cast<float4*>(out + (((size_t)n * C_ + c) * H_ + h) * W_ + w0) = o;
}

extern "C" void kernel_launch(void* const* d_in, const int* in_sizes, int n_in,
                              void* d_out, int out_size)
{
    const float* x   = (const float*)d_in[0];   // [8,256,64,64]
    const float* ker = (const float*)d_in[1];   // [8,1,9,64,64]
    float* out = (float*)d_out;                 // [8,256,64,64]

    dim3 block(16, 16);
    dim3 grid(N_ * H_, C_ / 16);
    ddf_kernel<<<grid, block>>>(x, ker, out);
}

// round 3
// speedup vs baseline: 1.4991x; 1.4991x over previous
#include <cuda_runtime.h>
#include <cstdint>

// DepthDCOp: out[n,c,h,w] = sum_{kh,kw} x_pad[n,c,h+kh-1,w+kw-1] * ker[n,0,kh*3+kw,h,w]
// N=8, C=256, H=64, W=64, K=3, dilation=1.

#define N_ 8
#define C_ 256
#define H_ 64
#define W_ 64
#define HW_ (H_ * W_)
#define CPT 4   // channels per thread

__global__ __launch_bounds__(256)
void ddf_kernel(const float* __restrict__ x,
                const float* __restrict__ ker,
                float* __restrict__ out)
{
    // grid.x = N*H (one (n,h) row per block), grid.y = C/(16*CPT)
    const int nh = blockIdx.x;
    const int n  = nh >> 6;          // /H_
    const int h  = nh & 63;          // %H_
    const int tx = threadIdx.x;      // 0..15 -> w quad
    const int ty = threadIdx.y;      // 0..15 -> channel group
    const int tid = ty * 16 + tx;

    // Stage the 9 per-pixel kernel rows for this (n,h): 9*64 floats = 2.25 KB,
    // read from DRAM once per block, reused by 64 channels.
    __shared__ float sk[9][W_];
    {
        const float4* kp = reinterpret_cast<const float4*>(
            ker + (size_t)n * 9 * HW_ + (size_t)h * W_);
        if (tid < 144) {
            const int t = tid >> 4;
            const int q = tid & 15;
            reinterpret_cast<float4*>(&sk[t][0])[q] = kp[(size_t)t * (HW_ / 4) + q];
        }
    }
    __syncthreads();

    const int w0 = tx << 2;

    // Hoist the 9 kernel taps for this quad into registers: 9 LDS.128,
    // amortized across CPT channels.
    float4 kv[9];
    #pragma unroll
    for (int t = 0; t < 9; t++)
        kv[t] = *reinterpret_cast<const float4*>(&sk[t][w0]);

    const int c0 = (blockIdx.y * (16 * CPT)) + ty * CPT;
    const bool up_ok   = (h > 0);
    const bool down_ok = (h < H_ - 1);

    #pragma unroll
    for (int ci = 0; ci < CPT; ci++) {
        const int c = c0 + ci;
        const float* xb = x + (((size_t)n * C_ + c) * H_ + h) * W_;

        // 3 rows of 4 body elements each (float4), halos via shuffle.
        float4 b[3];
        b[0] = up_ok   ? *reinterpret_cast<const float4*>(xb - W_ + w0)
                       : make_float4(0.f, 0.f, 0.f, 0.f);
        b[1] =           *reinterpret_cast<const float4*>(xb       + w0);
        b[2] = down_ok ? *reinterpret_cast<const float4*>(xb + W_ + w0)
                       : make_float4(0.f, 0.f, 0.f, 0.f);

        float lh[3], rh[3];
        #pragma unroll
        for (int r = 0; r < 3; r++) {
            // left neighbor = lane tx-1's body.w ; right = lane tx+1's body.x
            lh[r] = __shfl_up_sync(0xffffffffu,  b[r].w, 1, 16);
            rh[r] = __shfl_down_sync(0xffffffffu, b[r].x, 1, 16);
            if (tx == 0)  lh[r] = 0.f;   // w = -1 padding
            if (tx == 15) rh[r] = 0.f;   // w = 64 padding
        }

        float acc0 = 0.f, acc1 = 0.f, acc2 = 0.f, acc3 = 0.f;
        #pragma unroll
        for (int kh = 0; kh < 3; kh++) {
            // xr[kh][0..5] = { lh, b.x, b.y, b.z, b.w, rh }
            const float x0 = lh[kh], x1 = b[kh].x, x2 = b[kh].y,
                        x3 = b[kh].z, x4 = b[kh].w, x5 = rh[kh];
            #pragma unroll
            for (int kw = 0; kw < 3; kw++) {
                const int t = kh * 3 + kw;
                const float xa = (kw == 0) ? x0 : (kw == 1) ? x1 : x2;
                const float xb2= (kw == 0) ? x1 : (kw == 1) ? x2 : x3;
                const float xc = (kw == 0) ? x2 : (kw == 1) ? x3 : x4;
                const float xd = (kw == 0) ? x3 : (kw == 1) ? x4 : x5;
                acc0 = fmaf(kv[t].x, xa,  acc0);
                acc1 = fmaf(kv[t].y, xb2, acc1);
                acc2 = fmaf(kv[t].z, xc,  acc2);
                acc3 = fmaf(kv[t].w, xd,  acc3);
            }
        }

        float4 o; o.x = acc0; o.y = acc1; o.z = acc2; o.w = acc3;
        *reinterpret_cast<float4*>(
            out + (((size_t)n * C_ + c) * H_ + h) * W_ + w0) = o;
    }
}

extern "C" void kernel_launch(void* const* d_in, const int* in_sizes, int n_in,
                              void* d_out, int out_size)
{
    const float* x   = (const float*)d_in[0];   // [8,256,64,64]
    const float* ker = (const float*)d_in[1];   // [8,1,9,64,64]
    float* out = (float*)d_out;                 // [8,256,64,64]

    dim3 block(16, 16);
    dim3 grid(N_ * H_, C_ / (16 * CPT));
    ddf_kernel<<<grid, block>>>(x, ker, out);
}